// round 10
// baseline (speedup 1.0000x reference)
#include <cuda_runtime.h>
#include <cuda_bf16.h>

// Problem constants
#define BB 8
#define LL 8192
#define DD 512
#define SF 4
#define RR 32                 // rows per chunk
#define CH (LL / RR)          // 256 chunks per batch
#define NCHUNK (BB * CH)      // 2048 total chunks
#define OUT_L (LL / SF)       // 2048
#define D4 (DD / 4)           // 128 float4 lanes
#define OUTG (RR / SF)        // 8 output rows per chunk
#define NSUP 16               // supers per batch
#define SUPC (CH / NSUP)      // 16 chunks per super
#define GRIDN NCHUNK          // 2048 blocks, one chunk each, all co-resident

// Scratch (L2-resident)
__device__ float g_part[BB][CH][DD];        // per-chunk aggregates (4 MB)
__device__ float g_sup[BB][NSUP][DD];       // per-super sums (256 KB)
__device__ unsigned g_bar[2];               // barrier arrive counters
__device__ unsigned g_rel[2];               // barrier release flags

__device__ __forceinline__ unsigned ld_acq_u(const unsigned* p) {
    unsigned v;
    asm volatile("ld.acquire.gpu.u32 %0, [%1];" : "=r"(v) : "l"(p) : "memory");
    return v;
}

__global__ void k_reset() {
    if (threadIdx.x < 2) { g_bar[threadIdx.x] = 0u; g_rel[threadIdx.x] = 0u; }
}

// Grid barrier: safe because launch_bounds(64,16) guarantees 16 blocks/SM
// capacity (2048 <= 148*16), so all blocks are co-resident.
__device__ __forceinline__ void gsync(int i) {
    __syncthreads();
    if (threadIdx.x == 0) {
        __threadfence();
        unsigned v = atomicAdd(&g_bar[i], 1u);
        if (v == GRIDN - 1) {
            atomicExch(&g_rel[i], 1u);
        } else {
            while (ld_acq_u(&g_rel[i]) == 0u) __nanosleep(64);
        }
    }
    __syncthreads();
    __threadfence();
}

__global__ __launch_bounds__(64, 16) void k_all(const float* __restrict__ x,
                                                float* __restrict__ out) {
    const int tid = threadIdx.x;       // 0..63
    const int d40 = tid;               // first lane
    const int d41 = tid + 64;          // second lane (separate 512B warp segment)
    const int b = blockIdx.x >> 8;     // chunk id = blockIdx.x
    const int c = blockIdx.x & (CH - 1);

    const float4* xp = reinterpret_cast<const float4*>(
        x + ((size_t)b * LL + (size_t)c * RR) * DD);
    float4* op = reinterpret_cast<float4*>(
        out + ((size_t)b * OUT_L + (size_t)c * OUTG) * DD);

    // ── Phase A: local chunk scan; 8 independent LDG.128 in flight per batch ──
    float4 a0 = make_float4(0.f, 0.f, 0.f, 0.f);
    float4 a1 = make_float4(0.f, 0.f, 0.f, 0.f);
#pragma unroll
    for (int g = 0; g < OUTG; ++g) {
        const size_t r0 = (size_t)(g * SF) * D4;
        float4 u0 = __ldcs(xp + r0 + 0 * D4 + d40);
        float4 u1 = __ldcs(xp + r0 + 1 * D4 + d40);
        float4 u2 = __ldcs(xp + r0 + 2 * D4 + d40);
        float4 u3 = __ldcs(xp + r0 + 3 * D4 + d40);
        float4 w0 = __ldcs(xp + r0 + 0 * D4 + d41);
        float4 w1 = __ldcs(xp + r0 + 1 * D4 + d41);
        float4 w2 = __ldcs(xp + r0 + 2 * D4 + d41);
        float4 w3 = __ldcs(xp + r0 + 3 * D4 + d41);
        a0.x += (u0.x + u1.x) + (u2.x + u3.x);
        a0.y += (u0.y + u1.y) + (u2.y + u3.y);
        a0.z += (u0.z + u1.z) + (u2.z + u3.z);
        a0.w += (u0.w + u1.w) + (u2.w + u3.w);
        a1.x += (w0.x + w1.x) + (w2.x + w3.x);
        a1.y += (w0.y + w1.y) + (w2.y + w3.y);
        a1.z += (w0.z + w1.z) + (w2.z + w3.z);
        a1.w += (w0.w + w1.w) + (w2.w + w3.w);
        op[(size_t)g * D4 + d40] = a0;     // unscaled partial prefix
        op[(size_t)g * D4 + d41] = a1;
    }
    reinterpret_cast<float4*>(g_part[b][c])[d40] = a0;
    reinterpret_cast<float4*>(g_part[b][c])[d41] = a1;

    gsync(0);

    // ── Phase B: super sums (blocks 0..127) ──
    if (blockIdx.x < BB * NSUP) {
        const int sb = blockIdx.x >> 4;
        const int s = blockIdx.x & (NSUP - 1);
        float4 s0 = make_float4(0.f, 0.f, 0.f, 0.f);
        float4 s1 = make_float4(0.f, 0.f, 0.f, 0.f);
#pragma unroll
        for (int k = 0; k < SUPC; ++k) {
            const float4* pp = reinterpret_cast<const float4*>(g_part[sb][s * SUPC + k]);
            float4 v0 = pp[d40];
            float4 v1 = pp[d41];
            s0.x += v0.x; s0.y += v0.y; s0.z += v0.z; s0.w += v0.w;
            s1.x += v1.x; s1.y += v1.y; s1.z += v1.z; s1.w += v1.w;
        }
        reinterpret_cast<float4*>(g_sup[sb][s])[d40] = s0;
        reinterpret_cast<float4*>(g_sup[sb][s])[d41] = s1;
    }

    gsync(1);

    // ── Phase C: base from hierarchy (L2-hot), fix out in place ──
    const int s = c >> 4;
    const int nin = c & (SUPC - 1);
    float4 b0 = make_float4(0.f, 0.f, 0.f, 0.f);
    float4 b1 = make_float4(0.f, 0.f, 0.f, 0.f);
    for (int j = 0; j < s; ++j) {
        const float4* sp = reinterpret_cast<const float4*>(g_sup[b][j]);
        float4 v0 = sp[d40];
        float4 v1 = sp[d41];
        b0.x += v0.x; b0.y += v0.y; b0.z += v0.z; b0.w += v0.w;
        b1.x += v1.x; b1.y += v1.y; b1.z += v1.z; b1.w += v1.w;
    }
    for (int j = 0; j < nin; ++j) {
        const float4* pp = reinterpret_cast<const float4*>(g_part[b][s * SUPC + j]);
        float4 v0 = pp[d40];
        float4 v1 = pp[d41];
        b0.x += v0.x; b0.y += v0.y; b0.z += v0.z; b0.w += v0.w;
        b1.x += v1.x; b1.y += v1.y; b1.z += v1.z; b1.w += v1.w;
    }

#pragma unroll
    for (int g = 0; g < OUTG; ++g) {
        const float inv = 1.0f / (float)(c * RR + g * SF + SF);
        float4 v0 = op[(size_t)g * D4 + d40];
        float4 v1 = op[(size_t)g * D4 + d41];
        v0.x = (v0.x + b0.x) * inv;  v0.y = (v0.y + b0.y) * inv;
        v0.z = (v0.z + b0.z) * inv;  v0.w = (v0.w + b0.w) * inv;
        v1.x = (v1.x + b1.x) * inv;  v1.y = (v1.y + b1.y) * inv;
        v1.z = (v1.z + b1.z) * inv;  v1.w = (v1.w + b1.w) * inv;
        op[(size_t)g * D4 + d40] = v0;
        op[(size_t)g * D4 + d41] = v1;
    }
}

extern "C" void kernel_launch(void* const* d_in, const int* in_sizes, int n_in,
                              void* d_out, int out_size) {
    const float* x = (const float*)d_in[0];
    float* out = (float*)d_out;

    k_reset<<<1, 32>>>();
    k_all<<<GRIDN, 64>>>(x, out);
}